// round 9
// baseline (speedup 1.0000x reference)
#include <cuda_runtime.h>
#include <cuda_fp16.h>
#include <math.h>
#include <stdint.h>

// ---------------- dimensions ----------------
#define S_TOK 1024      // B*T
#define DD    2048
#define D3    6144
#define NB    64
#define NT    16
#define NH    8
#define DHD   256
#define NL    2
#define EE    32
#define HIDD  64
#define GO    32
#define NNODES (S_TOK*9)
#define KDIM  2048      // K for all GEMMs

// output layout (concatenated reference outputs, float32)
#define OUT_PHASE 0
#define OUT_LOC   3072
#define OUT_LES   10240
#define OUT_DIAG  17408
#define OUT_CONF  17856
#define OUT_ENT   17920

// GEMM tile config (single-fp16 mma.sync, baseline ISA)
#define BM 64
#define BN 128
#define GBK 32                         // k elements per chunk (64 bytes)
#define A_MATB (64*80)                 // 5120  (rows padded to 80B)
#define B_MATB (128*80)                // 10240
#define STAGE_BYTES (A_MATB + B_MATB)  // 15360
#define GSMEM (3*STAGE_BYTES)          // 46080
#define NCH   (KDIM/GBK)               // 64

// ---------------- scratch (static device memory; no allocations) ----------------
__device__ __align__(256) float g_x[S_TOK*DD];
__device__ __align__(256) float g_qkv[S_TOK*D3];
__device__ __align__(256) float g_tmp[S_TOK*DD];
__device__ int   g_phase[S_TOK];
__device__ int   g_locid[S_TOK];
__device__ int   g_les[S_TOK];
__device__ float g_score[S_TOK];
__device__ int   g_valid[S_TOK];
__device__ __align__(256) float g_pooled[NB*DD];
__device__ int   g_nxt[S_TOK];
__device__ int   g_prv[S_TOK];
__device__ float g_tp[3*HIDD];
__device__ float g_tl[7*HIDD];
__device__ float g_tle[7*HIDD];
__device__ __align__(256) float g_hw1[NNODES*HIDD];
__device__ __align__(256) float g_h1[NNODES*HIDD];
__device__ __align__(256) float g_hw2[NNODES*GO];
__device__ float g_nm[NNODES];
__device__ float g_deg[NNODES];
__device__ float g_dinv[NNODES];
__device__ float g_sm[S_TOK*GO];
__device__ float g_gp[NB*GO];

// fp16 weights (single) + fp16 activations
#define QKVW_E (2*6144*2048)
#define OW_E   (2*2048*2048)
__device__ __align__(256) __half g_qkvw[QKVW_E];
__device__ __align__(256) __half g_ow[OW_E];
__device__ __align__(256) __half g_f1[OW_E];
__device__ __align__(256) __half g_f2[OW_E];
__device__ __align__(256) __half g_ah[S_TOK*DD];   // act A (x / LN out)
__device__ __align__(256) __half g_bh[S_TOK*DD];   // act B (ctx / ff1 out)

// ---------------- PTX helpers (baseline ISA only) ----------------
__device__ __forceinline__ uint32_t smem_u32(const void* p){
    uint32_t a;
    asm("{ .reg .u64 t; cvta.to.shared.u64 t, %1; cvt.u32.u64 %0, t; }" : "=r"(a) : "l"(p));
    return a;
}
__device__ __forceinline__ void cp16(uint32_t dst, const void* src){
    asm volatile("cp.async.cg.shared.global [%0], [%1], 16;" :: "r"(dst), "l"(src));
}
__device__ __forceinline__ void cp_commit(){
    asm volatile("cp.async.commit_group;" ::: "memory");
}
__device__ __forceinline__ void cp_wait1(){
    asm volatile("cp.async.wait_group 1;" ::: "memory");
}
__device__ __forceinline__ void cp_wait0(){
    asm volatile("cp.async.wait_group 0;" ::: "memory");
}
__device__ __forceinline__ void ldsm_x4(uint32_t* r, uint32_t addr){
    asm volatile("ldmatrix.sync.aligned.m8n8.x4.shared.b16 {%0,%1,%2,%3}, [%4];"
        : "=r"(r[0]), "=r"(r[1]), "=r"(r[2]), "=r"(r[3]) : "r"(addr));
}
__device__ __forceinline__ void mma_f16(float* d, const uint32_t* a, const uint32_t* b){
    asm volatile("mma.sync.aligned.m16n8k16.row.col.f32.f16.f16.f32 "
        "{%0,%1,%2,%3}, {%4,%5,%6,%7}, {%8,%9}, {%0,%1,%2,%3};"
        : "+f"(d[0]), "+f"(d[1]), "+f"(d[2]), "+f"(d[3])
        : "r"(a[0]), "r"(a[1]), "r"(a[2]), "r"(a[3]), "r"(b[0]), "r"(b[1]));
}
__device__ __forceinline__ uint32_t pack_h2(float a, float b){
    __half2 t = __floats2half2_rn(a, b);
    return *(uint32_t*)&t;
}

// ---------------- weight fp32 -> fp16 convert ----------------
__global__ void k_cvt(const float4* __restrict__ src, uint2* __restrict__ dst, int n4){
    int i = blockIdx.x*blockDim.x + threadIdx.x;
    if (i >= n4) return;
    float4 v = src[i];
    uint2 H;
    H.x = pack_h2(v.x, v.y);
    H.y = pack_h2(v.z, v.w);
    dst[i] = H;
}

// ---------------- stage loader: A / B chunk (64 bytes per row) ----------
__device__ __forceinline__ void load_stage(uint32_t st,
    const __half* __restrict__ A, const __half* __restrict__ B, int tid)
{
    #pragma unroll
    for (int it = 0; it < 2; it++){
        int e = tid + it*128; int r = e >> 2, c4 = e & 3;
        cp16(st + r*80 + c4*16, A + (size_t)r*KDIM + c4*8);
    }
    #pragma unroll
    for (int it = 0; it < 4; it++){
        int e = tid + it*128; int r = e >> 2, c4 = e & 3;
        cp16(st + A_MATB + r*80 + c4*16, B + (size_t)r*KDIM + c4*8);
    }
    cp_commit();
}

// ---------------- fp16 GEMM: C = A @ B^T + bias --------------
// grid = (N/128, M/64), 128 threads (4 warps, warp tile 32x64), 3-stage pipe.
template<bool RELU, bool HALF_OUT>
__global__ void __launch_bounds__(128, 2)
gemm_h(const __half* __restrict__ A, const __half* __restrict__ B,
       const float* __restrict__ bias, float* __restrict__ C,
       __half* __restrict__ Oh, int N)
{
    extern __shared__ char smem[];
    uint32_t sb = smem_u32(smem);
    int tid = threadIdx.x;
    int warp = tid >> 5, lane = tid & 31;
    int m0 = blockIdx.y * BM;
    int n0 = blockIdx.x * BN;
    int warp_m = (warp >> 1) * 32;
    int warp_n = (warp & 1) * 64;

    const __half* pA = A + (size_t)m0*KDIM;
    const __half* pB = B + (size_t)n0*KDIM;

    float acc[2][8][4];
    #pragma unroll
    for (int i = 0; i < 2; i++)
        #pragma unroll
        for (int j = 0; j < 8; j++)
            #pragma unroll
            for (int q = 0; q < 4; q++) acc[i][j][q] = 0.f;

    load_stage(sb,               pA, pB, tid);
    load_stage(sb + STAGE_BYTES, pA + GBK, pB + GBK, tid);

    // byte addressing (validated f16-k16 fragment mapping)
    uint32_t a_base = (uint32_t)(warp_m + (lane & 15))*80 + (uint32_t)((lane >> 4)*16);
    uint32_t b_base = (uint32_t)(warp_n + ((lane >> 4) << 3) + (lane & 7))*80
                    + (uint32_t)(((lane >> 3) & 1)*16);

    int cur_s = 0, ld_s = 2;
    for (int c = 0; c < NCH; c++){
        if (c == NCH-1) cp_wait0(); else cp_wait1();
        __syncthreads();
        uint32_t st  = sb + cur_s*STAGE_BYTES;
        uint32_t a_b = st;
        uint32_t b_b = st + A_MATB;

        #pragma unroll
        for (int kk = 0; kk < 2; kk++){
            uint32_t kkB = kk*32;   // 16 halves = 32 bytes
            uint32_t af[2][4];
            #pragma unroll
            for (int mi = 0; mi < 2; mi++){
                ldsm_x4(af[mi], a_b + a_base + mi*16*80 + kkB);
            }
            uint32_t bf[8][2];
            #pragma unroll
            for (int ni2 = 0; ni2 < 4; ni2++){
                uint32_t t4[4];
                ldsm_x4(t4, b_b + b_base + ni2*16*80 + kkB);
                bf[ni2*2+0][0] = t4[0]; bf[ni2*2+0][1] = t4[1];
                bf[ni2*2+1][0] = t4[2]; bf[ni2*2+1][1] = t4[3];
            }
            #pragma unroll
            for (int mi = 0; mi < 2; mi++)
                #pragma unroll
                for (int ni = 0; ni < 8; ni++)
                    mma_f16(acc[mi][ni], af[mi], bf[ni]);
        }
        if (c + 2 < NCH){
            int cc = c + 2;
            load_stage(sb + ld_s*STAGE_BYTES, pA + cc*GBK, pB + cc*GBK, tid);
        }
        if (++cur_s == 3) cur_s = 0;
        if (++ld_s  == 3) ld_s  = 0;
    }

    // epilogue
    int er = lane >> 2;
    int ec = (lane & 3) * 2;
    #pragma unroll
    for (int mi = 0; mi < 2; mi++){
        int row0 = m0 + warp_m + mi*16 + er;
        #pragma unroll
        for (int ni = 0; ni < 8; ni++){
            int col = n0 + warp_n + ni*8 + ec;
            float b0 = bias[col], b1 = bias[col+1];
            float v00 = acc[mi][ni][0] + b0, v01 = acc[mi][ni][1] + b1;
            float v10 = acc[mi][ni][2] + b0, v11 = acc[mi][ni][3] + b1;
            if (RELU){
                v00 = fmaxf(v00, 0.f); v01 = fmaxf(v01, 0.f);
                v10 = fmaxf(v10, 0.f); v11 = fmaxf(v11, 0.f);
            }
            if (HALF_OUT){
                *(uint32_t*)(Oh + (size_t)row0*N + col)     = pack_h2(v00, v01);
                *(uint32_t*)(Oh + (size_t)(row0+8)*N + col) = pack_h2(v10, v11);
            } else {
                float2 w0; w0.x = v00; w0.y = v01;
                float2 w1; w1.x = v10; w1.y = v11;
                *(float2*)(C + (size_t)row0*N + col) = w0;
                *(float2*)(C + (size_t)(row0+8)*N + col) = w1;
            }
        }
    }
}

// ---------------- copy feat -> g_x + fp16 ----------------
__global__ void k_copy(const float4* __restrict__ src){
    int i = blockIdx.x*blockDim.x + threadIdx.x;
    float4 v = src[i];
    ((float4*)g_x)[i] = v;
    uint2 H;
    H.x = pack_h2(v.x, v.y);
    H.y = pack_h2(v.z, v.w);
    ((uint2*)g_ah)[i] = H;
}

// ---------------- per-token heads ----------------
__global__ void k_heads(const float* __restrict__ feat,
                        const float* __restrict__ wp, const float* __restrict__ bp,
                        const float* __restrict__ wl, const float* __restrict__ bl,
                        const float* __restrict__ wle, const float* __restrict__ ble,
                        float* __restrict__ out)
{
    int s = blockIdx.x;
    int tid = threadIdx.x;
    __shared__ float red[17][257];
    float acc[17];
    #pragma unroll
    for (int c = 0; c < 17; c++) acc[c] = 0.f;
    const float* frow = feat + (size_t)s*DD;
    for (int d = tid; d < DD; d += 256){
        float f = frow[d];
        #pragma unroll
        for (int c = 0; c < 3; c++) acc[c]    += f * wp[d*3+c];
        #pragma unroll
        for (int c = 0; c < 7; c++) acc[3+c]  += f * wl[d*7+c];
        #pragma unroll
        for (int c = 0; c < 7; c++) acc[10+c] += f * wle[d*7+c];
    }
    #pragma unroll
    for (int c = 0; c < 17; c++) red[c][tid] = acc[c];
    __syncthreads();
    for (int off = 128; off > 0; off >>= 1){
        if (tid < off){
            #pragma unroll
            for (int c = 0; c < 17; c++) red[c][tid] += red[c][tid+off];
        }
        __syncthreads();
    }
    if (tid == 0){
        float ph[3], lc[7], le[7];
        #pragma unroll
        for (int c = 0; c < 3; c++) ph[c] = red[c][0] + bp[c];
        #pragma unroll
        for (int c = 0; c < 7; c++) lc[c] = red[3+c][0] + bl[c];
        #pragma unroll
        for (int c = 0; c < 7; c++) le[c] = red[10+c][0] + ble[c];
        #pragma unroll
        for (int c = 0; c < 3; c++) out[OUT_PHASE + s*3 + c] = ph[c];
        #pragma unroll
        for (int c = 0; c < 7; c++) out[OUT_LOC + s*7 + c] = lc[c];
        #pragma unroll
        for (int c = 0; c < 7; c++) out[OUT_LES + s*7 + c] = le[c];
        int pid = 0; float bv = ph[0];
        #pragma unroll
        for (int c = 1; c < 3; c++) if (ph[c] > bv){ bv = ph[c]; pid = c; }
        int lidx = 0; bv = lc[0];
        #pragma unroll
        for (int c = 1; c < 7; c++) if (lc[c] > bv){ bv = lc[c]; lidx = c; }
        int bits = 0;
        #pragma unroll
        for (int c = 0; c < 7; c++) if (le[c] > 0.f) bits |= (1 << c);
        g_phase[s] = pid; g_locid[s] = lidx; g_les[s] = bits;
    }
}

// ---------------- attention (per b,h block) -> fp16 ctx into g_bh ----------------
__global__ void k_attn(const int* __restrict__ mask){
    int bh = blockIdx.x;
    int b = bh >> 3, hh = bh & 7;
    int tid = threadIdx.x;
    __shared__ float Qs[16*260];
    __shared__ float Ks[16*260];
    __shared__ float sc[16][17];
    int base = b*16;
    for (int i = tid; i < 2048; i += 256){
        int which = i >> 10;
        int w = i & 1023;
        int t = w >> 6, d4 = w & 63;
        float4 v = *(const float4*)&g_qkv[(size_t)(base+t)*D3 + which*DD + hh*DHD + d4*4];
        float* dstbase = which ? Ks : Qs;
        *(float4*)(dstbase + t*260 + d4*4) = v;
    }
    __syncthreads();
    {
        int q = tid >> 4, kk = tid & 15;
        const float4* qp = (const float4*)(Qs + q*260);
        const float4* kp = (const float4*)(Ks + kk*260);
        float a = 0.f;
        #pragma unroll 8
        for (int d4 = 0; d4 < 64; d4++){
            float4 x = qp[d4], y = kp[d4];
            a += x.x*y.x + x.y*y.y + x.z*y.z + x.w*y.w;
        }
        a *= 0.0625f;
        if (!mask[base+kk]) a = -1e9f;
        sc[q][kk] = a;
    }
    __syncthreads();
    if (tid < 16){
        float mx = -1e30f;
        #pragma unroll
        for (int k = 0; k < 16; k++) mx = fmaxf(mx, sc[tid][k]);
        float sm = 0.f;
        #pragma unroll
        for (int k = 0; k < 16; k++){ float e = expf(sc[tid][k]-mx); sc[tid][k] = e; sm += e; }
        float inv = 1.f/sm;
        #pragma unroll
        for (int k = 0; k < 16; k++) sc[tid][k] *= inv;
    }
    __syncthreads();
    float acc[16];
    #pragma unroll
    for (int t = 0; t < 16; t++) acc[t] = 0.f;
    #pragma unroll
    for (int k = 0; k < 16; k++){
        float vv = g_qkv[(size_t)(base+k)*D3 + 2*DD + hh*DHD + tid];
        #pragma unroll
        for (int t = 0; t < 16; t++) acc[t] += sc[t][k]*vv;
    }
    #pragma unroll
    for (int t = 0; t < 16; t++)
        g_bh[(size_t)(base+t)*DD + hh*DHD + tid] = __float2half_rn(acc[t]);
}

// ---------------- residual + layernorm + fp16 emit ----------------
__device__ __forceinline__ float blockReduceSum256(float v, float* red){
    int tid = threadIdx.x;
    red[tid] = v; __syncthreads();
    #pragma unroll
    for (int off = 128; off > 0; off >>= 1){
        if (tid < off) red[tid] += red[tid+off];
        __syncthreads();
    }
    float r = red[0];
    __syncthreads();
    return r;
}

__global__ void k_ln(const float* __restrict__ gam, const float* __restrict__ bet){
    int s = blockIdx.x, tid = threadIdx.x;
    __shared__ float y[DD];
    __shared__ float red[256];
    float part = 0.f;
    for (int d = tid; d < DD; d += 256){
        float v = g_x[(size_t)s*DD+d] + g_tmp[(size_t)s*DD+d];
        y[d] = v; part += v;
    }
    float m = blockReduceSum256(part, red) * (1.f/DD);
    part = 0.f;
    for (int d = tid; d < DD; d += 256){
        float v = y[d]-m; part += v*v;
    }
    float var = blockReduceSum256(part, red) * (1.f/DD);
    float inv = rsqrtf(var + 1e-5f);
    for (int d = tid; d < DD; d += 256){
        float v = (y[d]-m)*inv*gam[d] + bet[d];
        size_t idx = (size_t)s*DD+d;
        g_x[idx] = v;
        g_ah[idx] = __float2half_rn(v);
    }
}

// ---------------- scores ----------------
__global__ void k_scores(const float* __restrict__ w_score, const float* __restrict__ b_score){
    int s = blockIdx.x, tid = threadIdx.x;
    __shared__ float red[256];
    float part = 0.f;
    for (int d = tid; d < DD; d += 256) part += g_x[(size_t)s*DD+d]*w_score[d];
    float v = blockReduceSum256(part, red);
    if (tid == 0) g_score[s] = v + b_score[0];
}

// ---------------- per-batch softmax + pooled + valid ----------------
__global__ void k_pool(const int* __restrict__ mask){
    int b = blockIdx.x, tid = threadIdx.x;
    __shared__ float w[16];
    if (tid < 16){
        int s = b*16 + tid;
        w[tid] = mask[s] ? g_score[s] : -INFINITY;
    }
    __syncthreads();
    if (tid == 0){
        float mx = -INFINITY;
        #pragma unroll
        for (int t = 0; t < 16; t++) mx = fmaxf(mx, w[t]);
        float e[16], sm = 0.f;
        #pragma unroll
        for (int t = 0; t < 16; t++){ e[t] = expf(w[t]-mx); sm += e[t]; }
        float inv = 1.f/sm;
        #pragma unroll
        for (int t = 0; t < 16; t++) w[t] = e[t]*inv;
    }
    __syncthreads();
    if (tid < 16){
        int s = b*16 + tid;
        g_valid[s] = (mask[s] && w[tid] >= 0.05f) ? 1 : 0;
    }
    for (int d = tid; d < DD; d += 256){
        float acc = 0.f;
        #pragma unroll
        for (int t = 0; t < 16; t++) acc += w[t]*g_x[(size_t)(b*16+t)*DD+d];
        g_pooled[(size_t)b*DD+d] = acc;
    }
}

// ---------------- scan ----------------
__global__ void k_scan(){
    __shared__ unsigned char v[S_TOK];
    int i = threadIdx.x;
    v[i] = (unsigned char)g_valid[i];
    __syncthreads();
    int n = -1;
    for (int j = i+1; j < S_TOK; j++) if (v[j]){ n = j; break; }
    int p = -1;
    for (int j = i-1; j >= 0; j--) if (v[j]){ p = j; break; }
    g_nxt[i] = n; g_prv[i] = p;
}

// ---------------- node mask + degrees ----------------
__global__ void k_deg(){
    int s = blockIdx.x*blockDim.x + threadIdx.x;
    if (s >= S_TOK) return;
    float vv = g_valid[s] ? 1.f : 0.f;
    int lb = g_les[s];
    float m[9];
    m[0] = vv; m[1] = vv;
    #pragma unroll
    for (int k = 0; k < 7; k++) m[2+k] = (vv > 0.f && ((lb>>k)&1)) ? 1.f : 0.f;
    float sl = 0.f;
    #pragma unroll
    for (int k = 0; k < 7; k++) sl += m[2+k];
    float chain = ((g_valid[s] && g_nxt[s] >= 0) ? 1.f : 0.f)
                + ((g_valid[s] && g_prv[s] >= 0) ? 1.f : 0.f);
    float dg[9];
    dg[0] = 1.f + m[0]*m[1] + chain;
    dg[1] = 1.f + m[1]*(m[0] + sl);
    #pragma unroll
    for (int k = 0; k < 7; k++) dg[2+k] = 1.f + m[2+k]*(m[1] + sl - m[2+k]);
    #pragma unroll
    for (int j = 0; j < 9; j++){
        g_nm[s*9+j]  = m[j];
        g_deg[s*9+j] = dg[j];
        g_dinv[s*9+j]= rsqrtf(dg[j]);
    }
}

// ---------------- GCN tables ----------------
__global__ void k_tables(const float* __restrict__ emb_phase, const float* __restrict__ emb_loc,
                         const float* __restrict__ les_w, const float* __restrict__ les_b,
                         const float* __restrict__ W1){
    int idx = blockIdx.x*blockDim.x + threadIdx.x;
    if (idx >= 17*HIDD) return;
    int r = idx / HIDD, o = idx % HIDD;
    float acc = 0.f;
    if (r < 3){
        for (int e = 0; e < EE; e++) acc += emb_phase[r*EE+e]*W1[e*HIDD+o];
        g_tp[r*HIDD+o] = acc;
    } else if (r < 10){
        int rr = r-3;
        for (int e = 0; e < EE; e++) acc += emb_loc[rr*EE+e]*W1[e*HIDD+o];
        g_tl[rr*HIDD+o] = acc;
    } else {
        int rr = r-10;
        for (int e = 0; e < EE; e++) acc += (les_w[rr*EE+e]+les_b[e])*W1[e*HIDD+o];
        g_tle[rr*HIDD+o] = acc;
    }
}

// ---------------- scatter tables ----------------
__global__ void k_hw1(){
    int s = blockIdx.x, o = threadIdx.x;
    g_hw1[(size_t)(s*9+0)*HIDD+o] = g_tp[g_phase[s]*HIDD+o];
    g_hw1[(size_t)(s*9+1)*HIDD+o] = g_tl[g_locid[s]*HIDD+o];
    #pragma unroll
    for (int k = 0; k < 7; k++)
        g_hw1[(size_t)(s*9+2+k)*HIDD+o] = g_tle[k*HIDD+o];
}

// ---------------- GCN aggregation ----------------
template<int O, bool FUSE_SM>
__global__ void k_agg(const float* __restrict__ hw, const float* __restrict__ bias,
                      float* __restrict__ outp){
    int s = blockIdx.x, o = threadIdx.x;
    __shared__ float sh[9][O];
    __shared__ float m[9], dg[9], dv[9];
    #pragma unroll
    for (int j = 0; j < 9; j++) sh[j][o] = hw[(size_t)(s*9+j)*O+o];
    if (o < 9){
        m[o] = g_nm[s*9+o]; dg[o] = g_deg[s*9+o]; dv[o] = g_dinv[s*9+o];
    }
    int vld = g_valid[s];
    int nx = g_nxt[s], pv = g_prv[s];
    float hn = (vld && nx >= 0) ? hw[(size_t)(nx*9)*O+o]*g_dinv[nx*9] : 0.f;
    float hp = (vld && pv >= 0) ? hw[(size_t)(pv*9)*O+o]*g_dinv[pv*9] : 0.f;
    __syncthreads();

    float fv[9], hv[9];
    #pragma unroll
    for (int j = 0; j < 9; j++){ fv[j] = dv[j]*m[j]; hv[j] = sh[j][o]; }
    float sl = 0.f;
    #pragma unroll
    for (int j = 2; j < 9; j++) sl += fv[j]*hv[j];
    float b = bias[o];
    float h2[9];
    #pragma unroll
    for (int j = 0; j < 9; j++){
        float acc;
        if (j == 0)       acc = fv[1]*hv[1];
        else if (j == 1)  acc = fv[0]*hv[0] + sl;
        else              acc = fv[1]*hv[1] + sl - fv[j]*hv[j];
        acc *= m[j];
        if (j == 0) acc += hn + hp;
        float val = dv[j]*acc + hv[j]/dg[j] + b;
        val = fmaxf(val, 0.f);
        if (FUSE_SM) h2[j] = val;
        else outp[(size_t)(s*9+j)*O+o] = val;
    }
    if (FUSE_SM){
        float cnt = 0.f, smv = 0.f;
        #pragma unroll
        for (int j = 0; j < 9; j++){ cnt += m[j]; smv += h2[j]*m[j]; }
        outp[(size_t)s*O+o] = smv / fmaxf(cnt, 1.f);
    }
}

// ---------------- hW2 = h1 @ W2 ----------------
__global__ void k_mm2(const float* __restrict__ W2){
    int s = blockIdx.x;
    int tx = threadIdx.x;
    int ty = threadIdx.y;
    __shared__ float sh[9][HIDD];
    int lin = ty*32 + tx;
    for (int idx = lin; idx < 9*HIDD; idx += 288)
        sh[idx/HIDD][idx%HIDD] = g_h1[(size_t)(s*9)*HIDD + idx];
    __syncthreads();
    float acc = 0.f;
    #pragma unroll
    for (int k = 0; k < HIDD; k++) acc += sh[ty][k]*W2[k*GO+tx];
    g_hw2[(size_t)(s*9+ty)*GO+tx] = acc;
}

// ---------------- gnn pooled ----------------
__global__ void k_gnn_pool(){
    int b = blockIdx.x, o = threadIdx.x;
    float acc = 0.f, c = 0.f;
    #pragma unroll
    for (int t = 0; t < 16; t++){
        int s = b*16+t;
        if (g_valid[s]){ acc += g_sm[(size_t)s*GO+o]; c += 1.f; }
    }
    g_gp[(size_t)b*GO+o] = acc / fmaxf(c, 1.f);
}

// ---------------- diag head ----------------
__global__ void k_diag(const float* __restrict__ w_diag, const float* __restrict__ b_diag,
                       float* __restrict__ out){
    int b = blockIdx.x, tid = threadIdx.x;
    __shared__ float red[7][257];
    float acc[7];
    #pragma unroll
    for (int c = 0; c < 7; c++) acc[c] = 0.f;
    for (int d = tid; d < DD+GO; d += 256){
        float v = (d < DD) ? g_pooled[(size_t)b*DD+d] : g_gp[(size_t)b*GO + (d-DD)];
        #pragma unroll
        for (int c = 0; c < 7; c++) acc[c] += v*w_diag[d*7+c];
    }
    #pragma unroll
    for (int c = 0; c < 7; c++) red[c][tid] = acc[c];
    __syncthreads();
    for (int off = 128; off > 0; off >>= 1){
        if (tid < off){
            #pragma unroll
            for (int c = 0; c < 7; c++) red[c][tid] += red[c][tid+off];
        }
        __syncthreads();
    }
    if (tid == 0){
        float lg[7];
        #pragma unroll
        for (int c = 0; c < 7; c++){
            lg[c] = red[c][0] + b_diag[c];
            out[OUT_DIAG + b*7 + c] = lg[c];
        }
        float mx = lg[0];
        #pragma unroll
        for (int c = 1; c < 7; c++) mx = fmaxf(mx, lg[c]);
        float sm = 0.f;
        #pragma unroll
        for (int c = 0; c < 7; c++) sm += expf(lg[c]-mx);
        float inv = 1.f/sm;
        float conf = 0.f, ent = 0.f;
        #pragma unroll
        for (int c = 0; c < 7; c++){
            float p = expf(lg[c]-mx)*inv;
            conf = fmaxf(conf, p);
            ent -= p*logf(p + 1e-8f);
        }
        out[OUT_CONF + b] = conf;
        out[OUT_ENT  + b] = ent / logf(7.0f);
    }
}

// ---------------- launch ----------------
extern "C" void kernel_launch(void* const* d_in, const int* in_sizes, int n_in,
                              void* d_out, int out_size)
{
    const float* feat      = (const float*)d_in[0];
    const float* w_phase   = (const float*)d_in[1];
    const float* b_phase   = (const float*)d_in[2];
    const float* w_loc     = (const float*)d_in[3];
    const float* b_loc     = (const float*)d_in[4];
    const float* w_les     = (const float*)d_in[5];
    const float* b_les     = (const float*)d_in[6];
    const float* emb_phase = (const float*)d_in[7];
    const float* emb_loc   = (const float*)d_in[8];
    const float* les_emb_w = (const float*)d_in[9];
    const float* les_emb_b = (const float*)d_in[10];
    const float* qkv_w     = (const float*)d_in[11];
    const float* qkv_b     = (const float*)d_in[12];
    const float* o_w       = (const float*)d_in[13];
    const float* o_b       = (const float*)d_in[14];
    const float* ln1_g     = (const float*)d_in[15];
    const float* ln1_b     = (const float*)d_in[16];
    const float* ln2_g     = (const float*)d_in[17];
    const float* ln2_b     = (const float*)d_in[18];
    const float* ff1_w     = (const float*)d_in[19];
    const float* ff1_b     = (const float*)d_in[20];
    const float* ff2_w     = (const float*)d_in[21];
    const float* ff2_b     = (const float*)d_in[22];
    const float* w_score   = (const float*)d_in[23];
    const float* b_score   = (const float*)d_in[24];
    const float* gcn1_w    = (const float*)d_in[25];
    const float* gcn1_b    = (const float*)d_in[26];
    const float* gcn2_w    = (const float*)d_in[27];
    const float* gcn2_b    = (const float*)d_in[28];
    const float* w_diag    = (const float*)d_in[29];
    const float* b_diag    = (const float*)d_in[30];
    const int*   mask      = (const int*)  d_in[31];
    float* out = (float*)d_out;

    // resolve REAL device addresses (never pass __device__ symbols from host!)
    float *p_x, *p_qkv, *p_tmp, *p_hw1, *p_h1, *p_hw2, *p_sm;
    __half *p_qkvw, *p_ow, *p_f1, *p_f2, *p_ah, *p_bh;
    cudaGetSymbolAddress((void**)&p_x,    g_x);
    cudaGetSymbolAddress((void**)&p_qkv,  g_qkv);
    cudaGetSymbolAddress((void**)&p_tmp,  g_tmp);
    cudaGetSymbolAddress((void**)&p_hw1,  g_hw1);
    cudaGetSymbolAddress((void**)&p_h1,   g_h1);
    cudaGetSymbolAddress((void**)&p_hw2,  g_hw2);
    cudaGetSymbolAddress((void**)&p_sm,   g_sm);
    cudaGetSymbolAddress((void**)&p_qkvw, g_qkvw);
    cudaGetSymbolAddress((void**)&p_ow,   g_ow);
    cudaGetSymbolAddress((void**)&p_f1,   g_f1);
    cudaGetSymbolAddress((void**)&p_f2,   g_f2);
    cudaGetSymbolAddress((void**)&p_ah,   g_ah);
    cudaGetSymbolAddress((void**)&p_bh,   g_bh);

    cudaFuncSetAttribute(gemm_h<false,false>, cudaFuncAttributeMaxDynamicSharedMemorySize, GSMEM);
    cudaFuncSetAttribute(gemm_h<true,true>,   cudaFuncAttributeMaxDynamicSharedMemorySize, GSMEM);

    // x = feat (+ fp16)
    k_copy<<<(S_TOK*DD/4)/256, 256>>>((const float4*)feat);

    // weight fp16 converts
    k_cvt<<<QKVW_E/4/256, 256>>>((const float4*)qkv_w, (uint2*)p_qkvw, QKVW_E/4);
    k_cvt<<<OW_E/4/256, 256>>>((const float4*)o_w,   (uint2*)p_ow, OW_E/4);
    k_cvt<<<OW_E/4/256, 256>>>((const float4*)ff1_w, (uint2*)p_f1, OW_E/4);
    k_cvt<<<OW_E/4/256, 256>>>((const float4*)ff2_w, (uint2*)p_f2, OW_E/4);

    // per-token heads
    k_heads<<<S_TOK, 256>>>(feat, w_phase, b_phase, w_loc, b_loc, w_les, b_les, out);

    for (int l = 0; l < NL; l++){
        size_t wq = (size_t)l*D3*DD, bq = (size_t)l*D3;
        size_t wd = (size_t)l*DD*DD, bd = (size_t)l*DD;

        gemm_h<false,false><<<dim3(D3/BN, S_TOK/BM), 128, GSMEM>>>(
            p_ah, p_qkvw + wq, qkv_b + bq, p_qkv, nullptr, D3);
        k_attn<<<NB*NH, 256>>>(mask);   // -> fp16 ctx in g_bh

        gemm_h<false,false><<<dim3(DD/BN, S_TOK/BM), 128, GSMEM>>>(
            p_bh, p_ow + wd, o_b + bd, p_tmp, nullptr, DD);
        k_ln<<<S_TOK, 256>>>(ln1_g+bd, ln1_b+bd);   // -> g_x + fp16 g_ah

        gemm_h<true,true><<<dim3(DD/BN, S_TOK/BM), 128, GSMEM>>>(
            p_ah, p_f1 + wd, ff1_b + bd, nullptr, p_bh, DD);

        gemm_h<false,false><<<dim3(DD/BN, S_TOK/BM), 128, GSMEM>>>(
            p_bh, p_f2 + wd, ff2_b + bd, p_tmp, nullptr, DD);
        k_ln<<<S_TOK, 256>>>(ln2_g+bd, ln2_b+bd);   // -> g_x + fp16 g_ah
    }

    // pooling
    k_scores<<<S_TOK, 256>>>(w_score, b_score);
    k_pool<<<NB, 256>>>(mask);

    // GNN
    k_scan<<<1, S_TOK>>>();
    k_deg<<<4, 256>>>();
    k_tables<<<5, 256>>>(emb_phase, emb_loc, les_emb_w, les_emb_b, gcn1_w);
    k_hw1<<<S_TOK, HIDD>>>();
    k_agg<HIDD, false><<<S_TOK, HIDD>>>(p_hw1, gcn1_b, p_h1);
    k_mm2<<<S_TOK, dim3(32, 9)>>>(gcn2_w);
    k_agg<GO, true><<<S_TOK, GO>>>(p_hw2, gcn2_b, p_sm);
    k_gnn_pool<<<NB, GO>>>();

    // diagnosis head
    k_diag<<<NB, 256>>>(w_diag, b_diag, out);

    (void)in_sizes; (void)n_in; (void)out_size;
}

// round 10
// speedup vs baseline: 1.0061x; 1.0061x over previous
#include <cuda_runtime.h>
#include <cuda_fp16.h>
#include <math.h>
#include <stdint.h>

// ---------------- dimensions ----------------
#define S_TOK 1024      // B*T
#define DD    2048
#define D3    6144
#define NB    64
#define NT    16
#define NH    8
#define DHD   256
#define NL    2
#define EE    32
#define HIDD  64
#define GO    32
#define NNODES (S_TOK*9)
#define KDIM  2048      // K for all GEMMs

// output layout (concatenated reference outputs, float32)
#define OUT_PHASE 0
#define OUT_LOC   3072
#define OUT_LES   10240
#define OUT_DIAG  17408
#define OUT_CONF  17856
#define OUT_ENT   17920

// GEMM tile config (single-fp16 mma.sync, baseline ISA)
#define BM 64
#define BN 128
#define GBK 32                         // k elements per chunk (64 bytes)
#define A_MATB (64*80)                 // 5120  (rows padded to 80B)
#define B_MATB (128*80)                // 10240
#define STAGE_BYTES (A_MATB + B_MATB)  // 15360
#define GSMEM (3*STAGE_BYTES)          // 46080
#define NCH   (KDIM/GBK)               // 64

// ---------------- scratch (static device memory; no allocations) ----------------
__device__ __align__(256) float g_x[S_TOK*DD];
__device__ __align__(256) float g_qkv[S_TOK*D3];
__device__ __align__(256) float g_tmp[S_TOK*DD];
__device__ int   g_phase[S_TOK];
__device__ int   g_locid[S_TOK];
__device__ int   g_les[S_TOK];
__device__ float g_score[S_TOK];
__device__ int   g_valid[S_TOK];
__device__ __align__(256) float g_pooled[NB*DD];
__device__ int   g_nxt[S_TOK];
__device__ int   g_prv[S_TOK];
__device__ float g_tp[3*HIDD];
__device__ float g_tl[7*HIDD];
__device__ float g_tle[7*HIDD];
__device__ __align__(256) float g_hw1[NNODES*HIDD];
__device__ __align__(256) float g_h1[NNODES*HIDD];
__device__ __align__(256) float g_hw2[NNODES*GO];
__device__ float g_nm[NNODES];
__device__ float g_deg[NNODES];
__device__ float g_dinv[NNODES];
__device__ float g_sm[S_TOK*GO];
__device__ float g_gp[NB*GO];

// fp16 weights (single) + fp16 activations
#define QKVW_E (2*6144*2048)
#define OW_E   (2*2048*2048)
__device__ __align__(256) __half g_qkvw[QKVW_E];
__device__ __align__(256) __half g_ow[OW_E];
__device__ __align__(256) __half g_f1[OW_E];
__device__ __align__(256) __half g_f2[OW_E];
__device__ __align__(256) __half g_ah[S_TOK*DD];   // act A (x / LN out)
__device__ __align__(256) __half g_bh[S_TOK*DD];   // act B (ctx / ff1 out)

// ---------------- PTX helpers (baseline ISA only) ----------------
__device__ __forceinline__ uint32_t smem_u32(const void* p){
    uint32_t a;
    asm("{ .reg .u64 t; cvta.to.shared.u64 t, %1; cvt.u32.u64 %0, t; }" : "=r"(a) : "l"(p));
    return a;
}
__device__ __forceinline__ void cp16(uint32_t dst, const void* src){
    asm volatile("cp.async.cg.shared.global [%0], [%1], 16;" :: "r"(dst), "l"(src));
}
__device__ __forceinline__ void cp_commit(){
    asm volatile("cp.async.commit_group;" ::: "memory");
}
__device__ __forceinline__ void cp_wait1(){
    asm volatile("cp.async.wait_group 1;" ::: "memory");
}
__device__ __forceinline__ void cp_wait0(){
    asm volatile("cp.async.wait_group 0;" ::: "memory");
}
__device__ __forceinline__ void ldsm_x4(uint32_t* r, uint32_t addr){
    asm volatile("ldmatrix.sync.aligned.m8n8.x4.shared.b16 {%0,%1,%2,%3}, [%4];"
        : "=r"(r[0]), "=r"(r[1]), "=r"(r[2]), "=r"(r[3]) : "r"(addr));
}
__device__ __forceinline__ void mma_f16(float* d, const uint32_t* a, const uint32_t* b){
    asm volatile("mma.sync.aligned.m16n8k16.row.col.f32.f16.f16.f32 "
        "{%0,%1,%2,%3}, {%4,%5,%6,%7}, {%8,%9}, {%0,%1,%2,%3};"
        : "+f"(d[0]), "+f"(d[1]), "+f"(d[2]), "+f"(d[3])
        : "r"(a[0]), "r"(a[1]), "r"(a[2]), "r"(a[3]), "r"(b[0]), "r"(b[1]));
}
__device__ __forceinline__ uint32_t pack_h2(float a, float b){
    __half2 t = __floats2half2_rn(a, b);
    return *(uint32_t*)&t;
}

// ---------------- weight fp32 -> fp16 convert ----------------
__global__ void k_cvt(const float4* __restrict__ src, uint2* __restrict__ dst, int n4){
    int i = blockIdx.x*blockDim.x + threadIdx.x;
    if (i >= n4) return;
    float4 v = src[i];
    uint2 H;
    H.x = pack_h2(v.x, v.y);
    H.y = pack_h2(v.z, v.w);
    dst[i] = H;
}

// ---------------- stage loader: A / B chunk (64 bytes per row) ----------
__device__ __forceinline__ void load_stage(uint32_t st,
    const __half* __restrict__ A, const __half* __restrict__ B, int tid)
{
    #pragma unroll
    for (int it = 0; it < 2; it++){
        int e = tid + it*128; int r = e >> 2, c4 = e & 3;
        cp16(st + r*80 + c4*16, A + (size_t)r*KDIM + c4*8);
    }
    #pragma unroll
    for (int it = 0; it < 4; it++){
        int e = tid + it*128; int r = e >> 2, c4 = e & 3;
        cp16(st + A_MATB + r*80 + c4*16, B + (size_t)r*KDIM + c4*8);
    }
    cp_commit();
}

// ---------------- fp16 GEMM: C = A @ B^T + bias --------------
// grid = (N/128, M/64), 128 threads (4 warps, warp tile 32x64), 3-stage pipe.
template<bool RELU, bool HALF_OUT>
__global__ void __launch_bounds__(128, 2)
gemm_h(const __half* __restrict__ A, const __half* __restrict__ B,
       const float* __restrict__ bias, float* __restrict__ C,
       __half* __restrict__ Oh, int N)
{
    extern __shared__ char smem[];
    uint32_t sb = smem_u32(smem);
    int tid = threadIdx.x;
    int warp = tid >> 5, lane = tid & 31;
    int m0 = blockIdx.y * BM;
    int n0 = blockIdx.x * BN;
    int warp_m = (warp >> 1) * 32;
    int warp_n = (warp & 1) * 64;

    const __half* pA = A + (size_t)m0*KDIM;
    const __half* pB = B + (size_t)n0*KDIM;

    float acc[2][8][4];
    #pragma unroll
    for (int i = 0; i < 2; i++)
        #pragma unroll
        for (int j = 0; j < 8; j++)
            #pragma unroll
            for (int q = 0; q < 4; q++) acc[i][j][q] = 0.f;

    load_stage(sb,               pA, pB, tid);
    load_stage(sb + STAGE_BYTES, pA + GBK, pB + GBK, tid);

    // byte addressing (validated f16-k16 fragment mapping)
    uint32_t a_base = (uint32_t)(warp_m + (lane & 15))*80 + (uint32_t)((lane >> 4)*16);
    uint32_t b_base = (uint32_t)(warp_n + ((lane >> 4) << 3) + (lane & 7))*80
                    + (uint32_t)(((lane >> 3) & 1)*16);

    int cur_s = 0, ld_s = 2;
    for (int c = 0; c < NCH; c++){
        if (c == NCH-1) cp_wait0(); else cp_wait1();
        __syncthreads();
        uint32_t st  = sb + cur_s*STAGE_BYTES;
        uint32_t a_b = st;
        uint32_t b_b = st + A_MATB;

        #pragma unroll
        for (int kk = 0; kk < 2; kk++){
            uint32_t kkB = kk*32;   // 16 halves = 32 bytes
            uint32_t af[2][4];
            #pragma unroll
            for (int mi = 0; mi < 2; mi++){
                ldsm_x4(af[mi], a_b + a_base + mi*16*80 + kkB);
            }
            uint32_t bf[8][2];
            #pragma unroll
            for (int ni2 = 0; ni2 < 4; ni2++){
                uint32_t t4[4];
                ldsm_x4(t4, b_b + b_base + ni2*16*80 + kkB);
                bf[ni2*2+0][0] = t4[0]; bf[ni2*2+0][1] = t4[1];
                bf[ni2*2+1][0] = t4[2]; bf[ni2*2+1][1] = t4[3];
            }
            #pragma unroll
            for (int mi = 0; mi < 2; mi++)
                #pragma unroll
                for (int ni = 0; ni < 8; ni++)
                    mma_f16(acc[mi][ni], af[mi], bf[ni]);
        }
        if (c + 2 < NCH){
            int cc = c + 2;
            load_stage(sb + ld_s*STAGE_BYTES, pA + cc*GBK, pB + cc*GBK, tid);
        }
        if (++cur_s == 3) cur_s = 0;
        if (++ld_s  == 3) ld_s  = 0;
    }

    // epilogue
    int er = lane >> 2;
    int ec = (lane & 3) * 2;
    #pragma unroll
    for (int mi = 0; mi < 2; mi++){
        int row0 = m0 + warp_m + mi*16 + er;
        #pragma unroll
        for (int ni = 0; ni < 8; ni++){
            int col = n0 + warp_n + ni*8 + ec;
            float b0 = bias[col], b1 = bias[col+1];
            float v00 = acc[mi][ni][0] + b0, v01 = acc[mi][ni][1] + b1;
            float v10 = acc[mi][ni][2] + b0, v11 = acc[mi][ni][3] + b1;
            if (RELU){
                v00 = fmaxf(v00, 0.f); v01 = fmaxf(v01, 0.f);
                v10 = fmaxf(v10, 0.f); v11 = fmaxf(v11, 0.f);
            }
            if (HALF_OUT){
                *(uint32_t*)(Oh + (size_t)row0*N + col)     = pack_h2(v00, v01);
                *(uint32_t*)(Oh + (size_t)(row0+8)*N + col) = pack_h2(v10, v11);
            } else {
                float2 w0; w0.x = v00; w0.y = v01;
                float2 w1; w1.x = v10; w1.y = v11;
                *(float2*)(C + (size_t)row0*N + col) = w0;
                *(float2*)(C + (size_t)(row0+8)*N + col) = w1;
            }
        }
    }
}

// ---------------- copy feat -> g_x + fp16 ----------------
__global__ void k_copy(const float4* __restrict__ src){
    int i = blockIdx.x*blockDim.x + threadIdx.x;
    float4 v = src[i];
    ((float4*)g_x)[i] = v;
    uint2 H;
    H.x = pack_h2(v.x, v.y);
    H.y = pack_h2(v.z, v.w);
    ((uint2*)g_ah)[i] = H;
}

// ---------------- per-token heads ----------------
__global__ void k_heads(const float* __restrict__ feat,
                        const float* __restrict__ wp, const float* __restrict__ bp,
                        const float* __restrict__ wl, const float* __restrict__ bl,
                        const float* __restrict__ wle, const float* __restrict__ ble,
                        float* __restrict__ out)
{
    int s = blockIdx.x;
    int tid = threadIdx.x;
    __shared__ float red[17][257];
    float acc[17];
    #pragma unroll
    for (int c = 0; c < 17; c++) acc[c] = 0.f;
    const float* frow = feat + (size_t)s*DD;
    for (int d = tid; d < DD; d += 256){
        float f = frow[d];
        #pragma unroll
        for (int c = 0; c < 3; c++) acc[c]    += f * wp[d*3+c];
        #pragma unroll
        for (int c = 0; c < 7; c++) acc[3+c]  += f * wl[d*7+c];
        #pragma unroll
        for (int c = 0; c < 7; c++) acc[10+c] += f * wle[d*7+c];
    }
    #pragma unroll
    for (int c = 0; c < 17; c++) red[c][tid] = acc[c];
    __syncthreads();
    for (int off = 128; off > 0; off >>= 1){
        if (tid < off){
            #pragma unroll
            for (int c = 0; c < 17; c++) red[c][tid] += red[c][tid+off];
        }
        __syncthreads();
    }
    if (tid == 0){
        float ph[3], lc[7], le[7];
        #pragma unroll
        for (int c = 0; c < 3; c++) ph[c] = red[c][0] + bp[c];
        #pragma unroll
        for (int c = 0; c < 7; c++) lc[c] = red[3+c][0] + bl[c];
        #pragma unroll
        for (int c = 0; c < 7; c++) le[c] = red[10+c][0] + ble[c];
        #pragma unroll
        for (int c = 0; c < 3; c++) out[OUT_PHASE + s*3 + c] = ph[c];
        #pragma unroll
        for (int c = 0; c < 7; c++) out[OUT_LOC + s*7 + c] = lc[c];
        #pragma unroll
        for (int c = 0; c < 7; c++) out[OUT_LES + s*7 + c] = le[c];
        int pid = 0; float bv = ph[0];
        #pragma unroll
        for (int c = 1; c < 3; c++) if (ph[c] > bv){ bv = ph[c]; pid = c; }
        int lidx = 0; bv = lc[0];
        #pragma unroll
        for (int c = 1; c < 7; c++) if (lc[c] > bv){ bv = lc[c]; lidx = c; }
        int bits = 0;
        #pragma unroll
        for (int c = 0; c < 7; c++) if (le[c] > 0.f) bits |= (1 << c);
        g_phase[s] = pid; g_locid[s] = lidx; g_les[s] = bits;
    }
}

// ---------------- attention (per b,h block) -> fp16 ctx into g_bh ----------------
__global__ void k_attn(const int* __restrict__ mask){
    int bh = blockIdx.x;
    int b = bh >> 3, hh = bh & 7;
    int tid = threadIdx.x;
    __shared__ float Qs[16*260];
    __shared__ float Ks[16*260];
    __shared__ float sc[16][17];
    int base = b*16;
    for (int i = tid; i < 2048; i += 256){
        int which = i >> 10;
        int w = i & 1023;
        int t = w >> 6, d4 = w & 63;
        float4 v = *(const float4*)&g_qkv[(size_t)(base+t)*D3 + which*DD + hh*DHD + d4*4];
        float* dstbase = which ? Ks : Qs;
        *(float4*)(dstbase + t*260 + d4*4) = v;
    }
    __syncthreads();
    {
        int q = tid >> 4, kk = tid & 15;
        const float4* qp = (const float4*)(Qs + q*260);
        const float4* kp = (const float4*)(Ks + kk*260);
        float a = 0.f;
        #pragma unroll 8
        for (int d4 = 0; d4 < 64; d4++){
            float4 x = qp[d4], y = kp[d4];
            a += x.x*y.x + x.y*y.y + x.z*y.z + x.w*y.w;
        }
        a *= 0.0625f;
        if (!mask[base+kk]) a = -1e9f;
        sc[q][kk] = a;
    }
    __syncthreads();
    if (tid < 16){
        float mx = -1e30f;
        #pragma unroll
        for (int k = 0; k < 16; k++) mx = fmaxf(mx, sc[tid][k]);
        float sm = 0.f;
        #pragma unroll
        for (int k = 0; k < 16; k++){ float e = expf(sc[tid][k]-mx); sc[tid][k] = e; sm += e; }
        float inv = 1.f/sm;
        #pragma unroll
        for (int k = 0; k < 16; k++) sc[tid][k] *= inv;
    }
    __syncthreads();
    float acc[16];
    #pragma unroll
    for (int t = 0; t < 16; t++) acc[t] = 0.f;
    #pragma unroll
    for (int k = 0; k < 16; k++){
        float vv = g_qkv[(size_t)(base+k)*D3 + 2*DD + hh*DHD + tid];
        #pragma unroll
        for (int t = 0; t < 16; t++) acc[t] += sc[t][k]*vv;
    }
    #pragma unroll
    for (int t = 0; t < 16; t++)
        g_bh[(size_t)(base+t)*DD + hh*DHD + tid] = __float2half_rn(acc[t]);
}

// ---------------- residual + layernorm + fp16 emit ----------------
__device__ __forceinline__ float blockReduceSum256(float v, float* red){
    int tid = threadIdx.x;
    red[tid] = v; __syncthreads();
    #pragma unroll
    for (int off = 128; off > 0; off >>= 1){
        if (tid < off) red[tid] += red[tid+off];
        __syncthreads();
    }
    float r = red[0];
    __syncthreads();
    return r;
}

__global__ void k_ln(const float* __restrict__ gam, const float* __restrict__ bet){
    int s = blockIdx.x, tid = threadIdx.x;
    __shared__ float y[DD];
    __shared__ float red[256];
    float part = 0.f;
    for (int d = tid; d < DD; d += 256){
        float v = g_x[(size_t)s*DD+d] + g_tmp[(size_t)s*DD+d];
        y[d] = v; part += v;
    }
    float m = blockReduceSum256(part, red) * (1.f/DD);
    part = 0.f;
    for (int d = tid; d < DD; d += 256){
        float v = y[d]-m; part += v*v;
    }
    float var = blockReduceSum256(part, red) * (1.f/DD);
    float inv = rsqrtf(var + 1e-5f);
    for (int d = tid; d < DD; d += 256){
        float v = (y[d]-m)*inv*gam[d] + bet[d];
        size_t idx = (size_t)s*DD+d;
        g_x[idx] = v;
        g_ah[idx] = __float2half_rn(v);
    }
}

// ---------------- scores ----------------
__global__ void k_scores(const float* __restrict__ w_score, const float* __restrict__ b_score){
    int s = blockIdx.x, tid = threadIdx.x;
    __shared__ float red[256];
    float part = 0.f;
    for (int d = tid; d < DD; d += 256) part += g_x[(size_t)s*DD+d]*w_score[d];
    float v = blockReduceSum256(part, red);
    if (tid == 0) g_score[s] = v + b_score[0];
}

// ---------------- per-batch softmax + pooled + valid ----------------
__global__ void k_pool(const int* __restrict__ mask){
    int b = blockIdx.x, tid = threadIdx.x;
    __shared__ float w[16];
    if (tid < 16){
        int s = b*16 + tid;
        w[tid] = mask[s] ? g_score[s] : -INFINITY;
    }
    __syncthreads();
    if (tid == 0){
        float mx = -INFINITY;
        #pragma unroll
        for (int t = 0; t < 16; t++) mx = fmaxf(mx, w[t]);
        float e[16], sm = 0.f;
        #pragma unroll
        for (int t = 0; t < 16; t++){ e[t] = expf(w[t]-mx); sm += e[t]; }
        float inv = 1.f/sm;
        #pragma unroll
        for (int t = 0; t < 16; t++) w[t] = e[t]*inv;
    }
    __syncthreads();
    if (tid < 16){
        int s = b*16 + tid;
        g_valid[s] = (mask[s] && w[tid] >= 0.05f) ? 1 : 0;
    }
    for (int d = tid; d < DD; d += 256){
        float acc = 0.f;
        #pragma unroll
        for (int t = 0; t < 16; t++) acc += w[t]*g_x[(size_t)(b*16+t)*DD+d];
        g_pooled[(size_t)b*DD+d] = acc;
    }
}

// ---------------- scan ----------------
__global__ void k_scan(){
    __shared__ unsigned char v[S_TOK];
    int i = threadIdx.x;
    v[i] = (unsigned char)g_valid[i];
    __syncthreads();
    int n = -1;
    for (int j = i+1; j < S_TOK; j++) if (v[j]){ n = j; break; }
    int p = -1;
    for (int j = i-1; j >= 0; j--) if (v[j]){ p = j; break; }
    g_nxt[i] = n; g_prv[i] = p;
}

// ---------------- node mask + degrees ----------------
__global__ void k_deg(){
    int s = blockIdx.x*blockDim.x + threadIdx.x;
    if (s >= S_TOK) return;
    float vv = g_valid[s] ? 1.f : 0.f;
    int lb = g_les[s];
    float m[9];
    m[0] = vv; m[1] = vv;
    #pragma unroll
    for (int k = 0; k < 7; k++) m[2+k] = (vv > 0.f && ((lb>>k)&1)) ? 1.f : 0.f;
    float sl = 0.f;
    #pragma unroll
    for (int k = 0; k < 7; k++) sl += m[2+k];
    float chain = ((g_valid[s] && g_nxt[s] >= 0) ? 1.f : 0.f)
                + ((g_valid[s] && g_prv[s] >= 0) ? 1.f : 0.f);
    float dg[9];
    dg[0] = 1.f + m[0]*m[1] + chain;
    dg[1] = 1.f + m[1]*(m[0] + sl);
    #pragma unroll
    for (int k = 0; k < 7; k++) dg[2+k] = 1.f + m[2+k]*(m[1] + sl - m[2+k]);
    #pragma unroll
    for (int j = 0; j < 9; j++){
        g_nm[s*9+j]  = m[j];
        g_deg[s*9+j] = dg[j];
        g_dinv[s*9+j]= rsqrtf(dg[j]);
    }
}

// ---------------- GCN tables ----------------
__global__ void k_tables(const float* __restrict__ emb_phase, const float* __restrict__ emb_loc,
                         const float* __restrict__ les_w, const float* __restrict__ les_b,
                         const float* __restrict__ W1){
    int idx = blockIdx.x*blockDim.x + threadIdx.x;
    if (idx >= 17*HIDD) return;
    int r = idx / HIDD, o = idx % HIDD;
    float acc = 0.f;
    if (r < 3){
        for (int e = 0; e < EE; e++) acc += emb_phase[r*EE+e]*W1[e*HIDD+o];
        g_tp[r*HIDD+o] = acc;
    } else if (r < 10){
        int rr = r-3;
        for (int e = 0; e < EE; e++) acc += emb_loc[rr*EE+e]*W1[e*HIDD+o];
        g_tl[rr*HIDD+o] = acc;
    } else {
        int rr = r-10;
        for (int e = 0; e < EE; e++) acc += (les_w[rr*EE+e]+les_b[e])*W1[e*HIDD+o];
        g_tle[rr*HIDD+o] = acc;
    }
}

// ---------------- scatter tables ----------------
__global__ void k_hw1(){
    int s = blockIdx.x, o = threadIdx.x;
    g_hw1[(size_t)(s*9+0)*HIDD+o] = g_tp[g_phase[s]*HIDD+o];
    g_hw1[(size_t)(s*9+1)*HIDD+o] = g_tl[g_locid[s]*HIDD+o];
    #pragma unroll
    for (int k = 0; k < 7; k++)
        g_hw1[(size_t)(s*9+2+k)*HIDD+o] = g_tle[k*HIDD+o];
}

// ---------------- GCN aggregation ----------------
template<int O, bool FUSE_SM>
__global__ void k_agg(const float* __restrict__ hw, const float* __restrict__ bias,
                      float* __restrict__ outp){
    int s = blockIdx.x, o = threadIdx.x;
    __shared__ float sh[9][O];
    __shared__ float m[9], dg[9], dv[9];
    #pragma unroll
    for (int j = 0; j < 9; j++) sh[j][o] = hw[(size_t)(s*9+j)*O+o];
    if (o < 9){
        m[o] = g_nm[s*9+o]; dg[o] = g_deg[s*9+o]; dv[o] = g_dinv[s*9+o];
    }
    int vld = g_valid[s];
    int nx = g_nxt[s], pv = g_prv[s];
    float hn = (vld && nx >= 0) ? hw[(size_t)(nx*9)*O+o]*g_dinv[nx*9] : 0.f;
    float hp = (vld && pv >= 0) ? hw[(size_t)(pv*9)*O+o]*g_dinv[pv*9] : 0.f;
    __syncthreads();

    float fv[9], hv[9];
    #pragma unroll
    for (int j = 0; j < 9; j++){ fv[j] = dv[j]*m[j]; hv[j] = sh[j][o]; }
    float sl = 0.f;
    #pragma unroll
    for (int j = 2; j < 9; j++) sl += fv[j]*hv[j];
    float b = bias[o];
    float h2[9];
    #pragma unroll
    for (int j = 0; j < 9; j++){
        float acc;
        if (j == 0)       acc = fv[1]*hv[1];
        else if (j == 1)  acc = fv[0]*hv[0] + sl;
        else              acc = fv[1]*hv[1] + sl - fv[j]*hv[j];
        acc *= m[j];
        if (j == 0) acc += hn + hp;
        float val = dv[j]*acc + hv[j]/dg[j] + b;
        val = fmaxf(val, 0.f);
        if (FUSE_SM) h2[j] = val;
        else outp[(size_t)(s*9+j)*O+o] = val;
    }
    if (FUSE_SM){
        float cnt = 0.f, smv = 0.f;
        #pragma unroll
        for (int j = 0; j < 9; j++){ cnt += m[j]; smv += h2[j]*m[j]; }
        outp[(size_t)s*O+o] = smv / fmaxf(cnt, 1.f);
    }
}

// ---------------- hW2 = h1 @ W2 ----------------
__global__ void k_mm2(const float* __restrict__ W2){
    int s = blockIdx.x;
    int tx = threadIdx.x;
    int ty = threadIdx.y;
    __shared__ float sh[9][HIDD];
    int lin = ty*32 + tx;
    for (int idx = lin; idx < 9*HIDD; idx += 288)
        sh[idx/HIDD][idx%HIDD] = g_h1[(size_t)(s*9)*HIDD + idx];
    __syncthreads();
    float acc = 0.f;
    #pragma unroll
    for (int k = 0; k < HIDD; k++) acc += sh[ty][k]*W2[k*GO+tx];
    g_hw2[(size_t)(s*9+ty)*GO+tx] = acc;
}

// ---------------- gnn pooled ----------------
__global__ void k_gnn_pool(){
    int b = blockIdx.x, o = threadIdx.x;
    float acc = 0.f, c = 0.f;
    #pragma unroll
    for (int t = 0; t < 16; t++){
        int s = b*16+t;
        if (g_valid[s]){ acc += g_sm[(size_t)s*GO+o]; c += 1.f; }
    }
    g_gp[(size_t)b*GO+o] = acc / fmaxf(c, 1.f);
}

// ---------------- diag head ----------------
__global__ void k_diag(const float* __restrict__ w_diag, const float* __restrict__ b_diag,
                       float* __restrict__ out){
    int b = blockIdx.x, tid = threadIdx.x;
    __shared__ float red[7][257];
    float acc[7];
    #pragma unroll
    for (int c = 0; c < 7; c++) acc[c] = 0.f;
    for (int d = tid; d < DD+GO; d += 256){
        float v = (d < DD) ? g_pooled[(size_t)b*DD+d] : g_gp[(size_t)b*GO + (d-DD)];
        #pragma unroll
        for (int c = 0; c < 7; c++) acc[c] += v*w_diag[d*7+c];
    }
    #pragma unroll
    for (int c = 0; c < 7; c++) red[c][tid] = acc[c];
    __syncthreads();
    for (int off = 128; off > 0; off >>= 1){
        if (tid < off){
            #pragma unroll
            for (int c = 0; c < 7; c++) red[c][tid] += red[c][tid+off];
        }
        __syncthreads();
    }
    if (tid == 0){
        float lg[7];
        #pragma unroll
        for (int c = 0; c < 7; c++){
            lg[c] = red[c][0] + b_diag[c];
            out[OUT_DIAG + b*7 + c] = lg[c];
        }
        float mx = lg[0];
        #pragma unroll
        for (int c = 1; c < 7; c++) mx = fmaxf(mx, lg[c]);
        float sm = 0.f;
        #pragma unroll
        for (int c = 0; c < 7; c++) sm += expf(lg[c]-mx);
        float inv = 1.f/sm;
        float conf = 0.f, ent = 0.f;
        #pragma unroll
        for (int c = 0; c < 7; c++){
            float p = expf(lg[c]-mx)*inv;
            conf = fmaxf(conf, p);
            ent -= p*logf(p + 1e-8f);
        }
        out[OUT_CONF + b] = conf;
        out[OUT_ENT  + b] = ent / logf(7.0f);
    }
}

// ---------------- launch ----------------
extern "C" void kernel_launch(void* const* d_in, const int* in_sizes, int n_in,
                              void* d_out, int out_size)
{
    const float* feat      = (const float*)d_in[0];
    const float* w_phase   = (const float*)d_in[1];
    const float* b_phase   = (const float*)d_in[2];
    const float* w_loc     = (const float*)d_in[3];
    const float* b_loc     = (const float*)d_in[4];
    const float* w_les     = (const float*)d_in[5];
    const float* b_les     = (const float*)d_in[6];
    const float* emb_phase = (const float*)d_in[7];
    const float* emb_loc   = (const float*)d_in[8];
    const float* les_emb_w = (const float*)d_in[9];
    const float* les_emb_b = (const float*)d_in[10];
    const float* qkv_w     = (const float*)d_in[11];
    const float* qkv_b     = (const float*)d_in[12];
    const float* o_w       = (const float*)d_in[13];
    const float* o_b       = (const float*)d_in[14];
    const float* ln1_g     = (const float*)d_in[15];
    const float* ln1_b     = (const float*)d_in[16];
    const float* ln2_g     = (const float*)d_in[17];
    const float* ln2_b     = (const float*)d_in[18];
    const float* ff1_w     = (const float*)d_in[19];
    const float* ff1_b     = (const float*)d_in[20];
    const float* ff2_w     = (const float*)d_in[21];
    const float* ff2_b     = (const float*)d_in[22];
    const float* w_score   = (const float*)d_in[23];
    const float* b_score   = (const float*)d_in[24];
    const float* gcn1_w    = (const float*)d_in[25];
    const float* gcn1_b    = (const float*)d_in[26];
    const float* gcn2_w    = (const float*)d_in[27];
    const float* gcn2_b    = (const float*)d_in[28];
    const float* w_diag    = (const float*)d_in[29];
    const float* b_diag    = (const float*)d_in[30];
    const int*   mask      = (const int*)  d_in[31];
    float* out = (float*)d_out;

    // resolve REAL device addresses (never pass __device__ symbols from host!)
    float *p_x, *p_qkv, *p_tmp, *p_hw1, *p_h1, *p_hw2, *p_sm;
    __half *p_qkvw, *p_ow, *p_f1, *p_f2, *p_ah, *p_bh;
    cudaGetSymbolAddress((void**)&p_x,    g_x);
    cudaGetSymbolAddress((void**)&p_qkv,  g_qkv);
    cudaGetSymbolAddress((void**)&p_tmp,  g_tmp);
    cudaGetSymbolAddress((void**)&p_hw1,  g_hw1);
    cudaGetSymbolAddress((void**)&p_h1,   g_h1);
    cudaGetSymbolAddress((void**)&p_hw2,  g_hw2);
    cudaGetSymbolAddress((void**)&p_sm,   g_sm);
    cudaGetSymbolAddress((void**)&p_qkvw, g_qkvw);
    cudaGetSymbolAddress((void**)&p_ow,   g_ow);
    cudaGetSymbolAddress((void**)&p_f1,   g_f1);
    cudaGetSymbolAddress((void**)&p_f2,   g_f2);
    cudaGetSymbolAddress((void**)&p_ah,   g_ah);
    cudaGetSymbolAddress((void**)&p_bh,   g_bh);

    cudaFuncSetAttribute(gemm_h<false,false>, cudaFuncAttributeMaxDynamicSharedMemorySize, GSMEM);
    cudaFuncSetAttribute(gemm_h<true,true>,   cudaFuncAttributeMaxDynamicSharedMemorySize, GSMEM);

    // x = feat (+ fp16)
    k_copy<<<(S_TOK*DD/4)/256, 256>>>((const float4*)feat);

    // weight fp16 converts
    k_cvt<<<QKVW_E/4/256, 256>>>((const float4*)qkv_w, (uint2*)p_qkvw, QKVW_E/4);
    k_cvt<<<OW_E/4/256, 256>>>((const float4*)o_w,   (uint2*)p_ow, OW_E/4);
    k_cvt<<<OW_E/4/256, 256>>>((const float4*)ff1_w, (uint2*)p_f1, OW_E/4);
    k_cvt<<<OW_E/4/256, 256>>>((const float4*)ff2_w, (uint2*)p_f2, OW_E/4);

    // per-token heads
    k_heads<<<S_TOK, 256>>>(feat, w_phase, b_phase, w_loc, b_loc, w_les, b_les, out);

    for (int l = 0; l < NL; l++){
        size_t wq = (size_t)l*D3*DD, bq = (size_t)l*D3;
        size_t wd = (size_t)l*DD*DD, bd = (size_t)l*DD;

        gemm_h<false,false><<<dim3(D3/BN, S_TOK/BM), 128, GSMEM>>>(
            p_ah, p_qkvw + wq, qkv_b + bq, p_qkv, nullptr, D3);
        k_attn<<<NB*NH, 256>>>(mask);   // -> fp16 ctx in g_bh

        gemm_h<false,false><<<dim3(DD/BN, S_TOK/BM), 128, GSMEM>>>(
            p_bh, p_ow + wd, o_b + bd, p_tmp, nullptr, DD);
        k_ln<<<S_TOK, 256>>>(ln1_g+bd, ln1_b+bd);   // -> g_x + fp16 g_ah

        gemm_h<true,true><<<dim3(DD/BN, S_TOK/BM), 128, GSMEM>>>(
            p_ah, p_f1 + wd, ff1_b + bd, nullptr, p_bh, DD);

        gemm_h<false,false><<<dim3(DD/BN, S_TOK/BM), 128, GSMEM>>>(
            p_bh, p_f2 + wd, ff2_b + bd, p_tmp, nullptr, DD);
        k_ln<<<S_TOK, 256>>>(ln2_g+bd, ln2_b+bd);   // -> g_x + fp16 g_ah
    }

    // pooling
    k_scores<<<S_TOK, 256>>>(w_score, b_score);
    k_pool<<<NB, 256>>>(mask);

    // GNN
    k_scan<<<1, S_TOK>>>();
    k_deg<<<4, 256>>>();
    k_tables<<<5, 256>>>(emb_phase, emb_loc, les_emb_w, les_emb_b, gcn1_w);
    k_hw1<<<S_TOK, HIDD>>>();
    k_agg<HIDD, false><<<S_TOK, HIDD>>>(p_hw1, gcn1_b, p_h1);
    k_mm2<<<S_TOK, dim3(32, 9)>>>(gcn2_w);
    k_agg<GO, true><<<S_TOK, GO>>>(p_hw2, gcn2_b, p_sm);
    k_gnn_pool<<<NB, GO>>>();

    // diagnosis head
    k_diag<<<NB, 256>>>(w_diag, b_diag, out);

    (void)in_sizes; (void)n_in; (void)out_size;
}